// round 5
// baseline (speedup 1.0000x reference)
#include <cuda_runtime.h>
#include <math.h>

#define B_   4
#define N_   4096
#define DIMM 1024
#define HEADS 16
#define HD   64
#define ROWS (B_*N_)          // 16384

// ---------------- scratch (device globals: allocation-free) ----------------
// g_qkv holds x@w_qkv (192 MB). After rope_elu consumes it, its storage is
// dead, so the attention output aliases its first 64 MB.
__device__ float g_qkv[(size_t)ROWS * 3 * DIMM];       // 192 MB (attn reuses)
__device__ float g_qf [(size_t)B_*HEADS*N_*HD];        // featurized Q   64 MB
__device__ float g_kf [(size_t)B_*HEADS*N_*HD];        // featurized K   64 MB
__device__ float g_vf [(size_t)B_*HEADS*N_*HD];        // V (B,H,N,D)    64 MB

// ---------------- fp32 SGEMM: 128x128 tile, 8x8 microtile, BK=8 ------------
__global__ void __launch_bounds__(256) sgemm128(const float* __restrict__ A,
                                                const float* __restrict__ Bm,
                                                float* __restrict__ C,
                                                int M, int N, int K) {
    __shared__ float As[8][128];   // transposed A tile: As[k][m]
    __shared__ float Bs[8][128];   // Bs[k][n]
    const int tid = threadIdx.x;
    const int m0 = blockIdx.y * 128;
    const int n0 = blockIdx.x * 128;
    const int arow = tid >> 1, acol = (tid & 1) * 4;
    const int brow = tid >> 5, bcol = (tid & 31) * 4;
    const int tx = tid & 15, ty = tid >> 4;

    float acc[8][8];
#pragma unroll
    for (int i = 0; i < 8; i++)
#pragma unroll
        for (int j = 0; j < 8; j++) acc[i][j] = 0.f;

    const float* Ap = A + (size_t)(m0 + arow) * K + acol;
    const float* Bp = Bm + n0 + bcol;

    for (int k0 = 0; k0 < K; k0 += 8) {
        float4 av = *(const float4*)(Ap + k0);
        float4 bv = *(const float4*)(Bp + (size_t)(k0 + brow) * N);
        As[acol + 0][arow] = av.x;
        As[acol + 1][arow] = av.y;
        As[acol + 2][arow] = av.z;
        As[acol + 3][arow] = av.w;
        *(float4*)&Bs[brow][bcol] = bv;
        __syncthreads();
#pragma unroll
        for (int kk = 0; kk < 8; kk++) {
            float ra[8], rb[8];
            *(float4*)&ra[0] = *(float4*)&As[kk][ty * 4];
            *(float4*)&ra[4] = *(float4*)&As[kk][64 + ty * 4];
            *(float4*)&rb[0] = *(float4*)&Bs[kk][tx * 4];
            *(float4*)&rb[4] = *(float4*)&Bs[kk][64 + tx * 4];
#pragma unroll
            for (int i = 0; i < 8; i++)
#pragma unroll
                for (int j = 0; j < 8; j++) acc[i][j] += ra[i] * rb[j];
        }
        __syncthreads();
    }
#pragma unroll
    for (int i = 0; i < 8; i++) {
        int r = m0 + ((i < 4) ? (ty * 4 + i) : (64 + ty * 4 + (i - 4)));
        float4 v0 = make_float4(acc[i][0], acc[i][1], acc[i][2], acc[i][3]);
        float4 v1 = make_float4(acc[i][4], acc[i][5], acc[i][6], acc[i][7]);
        *(float4*)(C + (size_t)r * N + n0 + tx * 4) = v0;
        *(float4*)(C + (size_t)r * N + n0 + 64 + tx * 4) = v1;
    }
}

// ---------------- RoPE + ELU feature map + transpose to (B,H,N,D) ----------
__global__ void rope_elu(const float* __restrict__ qkv,
                         float* __restrict__ qf, float* __restrict__ kf,
                         float* __restrict__ vf) {
    int idx = blockIdx.x * blockDim.x + threadIdx.x;  // over B*N*H*32 pairs
    const int total = B_ * N_ * HEADS * 32;
    if (idx >= total) return;
    const int d2 = idx & 31;
    const int h  = (idx >> 5) & 15;
    const int n  = (idx >> 9) & 4095;
    const int b  = idx >> 21;

    size_t base = (size_t)(b * N_ + n) * (3 * DIMM);
    int c1 = h * 64 + d2;
    float q1 = qkv[base + c1],            q2 = qkv[base + c1 + 32];
    float k1 = qkv[base + 1024 + c1],     k2 = qkv[base + 1024 + c1 + 32];
    float v1 = qkv[base + 2048 + c1],     v2 = qkv[base + 2048 + c1 + 32];

    float inv = powf(10000.f, -(float)d2 * (1.f / 32.f));
    float ang = (float)n * inv;
    float cs = cosf(ang), sn = sinf(ang);
    float qr1 = q1 * cs - q2 * sn, qr2 = q1 * sn + q2 * cs;
    float kr1 = k1 * cs - k2 * sn, kr2 = k1 * sn + k2 * cs;

    const float SC = 0.35355339059327373f;  // 64^(-1/4)
    // elu(x*SC)+1 : x>0 -> x*SC+1 ; else exp(x*SC)
    float y;
    y = qr1 * SC; float fq1 = (y > 0.f) ? y + 1.f : expf(y);
    y = qr2 * SC; float fq2 = (y > 0.f) ? y + 1.f : expf(y);
    y = kr1 * SC; float fk1 = (y > 0.f) ? y + 1.f : expf(y);
    y = kr2 * SC; float fk2 = (y > 0.f) ? y + 1.f : expf(y);

    size_t ob = ((size_t)(b * HEADS + h) * N_ + n) * HD;
    qf[ob + d2] = fq1;  qf[ob + d2 + 32] = fq2;
    kf[ob + d2] = fk1;  kf[ob + d2 + 32] = fk2;
    vf[ob + d2] = v1;   vf[ob + d2 + 32] = v2;
}

// ---------------- chunked causal linear attention ---------------------------
// One block per (b,h). 64 chunks of 64 rows. State KV[64][64], ks[64] in smem.
#define ATTN_SMEM (6 * 4096 * 4 + 128 * 4)
__global__ void __launch_bounds__(256) linattn(const float* __restrict__ qf,
                                               const float* __restrict__ kf,
                                               const float* __restrict__ vf,
                                               float* __restrict__ outp) {
    extern __shared__ float sm[];
    float* QsT = sm;              // [d][i]
    float* Ks  = QsT + 4096;      // [i][d]
    float* KsT = Ks + 4096;       // [d][j]
    float* Vs  = KsT + 4096;      // [j][m]
    float* STs = Vs + 4096;       // [j][i]  (masked S transposed)
    float* KV  = STs + 4096;      // [d][m]
    float* kss = KV + 4096;       // [64]
    float* den = kss + 64;        // [64]

    const int tid = threadIdx.x;
    const int bh = blockIdx.x;
    const int b = bh >> 4, h = bh & 15;
    const float* qb = qf + (size_t)bh * N_ * HD;
    const float* kb = kf + (size_t)bh * N_ * HD;
    const float* vb = vf + (size_t)bh * N_ * HD;
    float* ob = outp + (size_t)b * N_ * DIMM + h * HD;

    for (int i = tid; i < 4096; i += 256) KV[i] = 0.f;
    if (tid < 64) kss[tid] = 0.f;
    __syncthreads();

    const int li = tid >> 2, lq = (tid & 3) * 16;    // load mapping
    const int g1 = tid >> 4, g2 = tid & 15;          // compute mapping

    for (int c = 0; c < 64; c++) {
        const int n0 = c * 64;
        // ---- load chunk (Q transposed, K both layouts, V) ----
        {
            const float* qrow = qb + (size_t)(n0 + li) * HD + lq;
            const float* krow = kb + (size_t)(n0 + li) * HD + lq;
            const float* vrow = vb + (size_t)(n0 + li) * HD + lq;
#pragma unroll
            for (int t = 0; t < 4; t++) {
                int d0 = lq + t * 4;
                float4 qv = *(const float4*)(qrow + t * 4);
                QsT[(d0 + 0) * 64 + li] = qv.x;
                QsT[(d0 + 1) * 64 + li] = qv.y;
                QsT[(d0 + 2) * 64 + li] = qv.z;
                QsT[(d0 + 3) * 64 + li] = qv.w;
                float4 kv4 = *(const float4*)(krow + t * 4);
                *(float4*)&Ks[li * 64 + d0] = kv4;
                KsT[(d0 + 0) * 64 + li] = kv4.x;
                KsT[(d0 + 1) * 64 + li] = kv4.y;
                KsT[(d0 + 2) * 64 + li] = kv4.z;
                KsT[(d0 + 3) * 64 + li] = kv4.w;
                float4 vv = *(const float4*)(vrow + t * 4);
                *(float4*)&Vs[li * 64 + d0] = vv;
            }
        }
        __syncthreads();
        // ---- S^T[j][i] = sum_d Q[i][d] K[j][d], causal mask j<=i ----
        {
            float accS[16];
#pragma unroll
            for (int z = 0; z < 16; z++) accS[z] = 0.f;
            for (int d = 0; d < 64; d++) {
                float4 qv = *(float4*)&QsT[d * 64 + g2 * 4];
                float4 kk = *(float4*)&KsT[d * 64 + g1 * 4];
                float qa[4] = {qv.x, qv.y, qv.z, qv.w};
                float ka[4] = {kk.x, kk.y, kk.z, kk.w};
#pragma unroll
                for (int jj = 0; jj < 4; jj++)
#pragma unroll
                    for (int ii = 0; ii < 4; ii++)
                        accS[jj * 4 + ii] += ka[jj] * qa[ii];
            }
#pragma unroll
            for (int jj = 0; jj < 4; jj++)
#pragma unroll
                for (int ii = 0; ii < 4; ii++) {
                    int j = g1 * 4 + jj, i = g2 * 4 + ii;
                    STs[j * 64 + i] = (j <= i) ? accS[jj * 4 + ii] : 0.f;
                }
        }
        __syncthreads();
        // ---- denom[i] = max(q_i . ks_prev + rowsum_{j<=i} S, 1e-6) ----
        if (tid < 64) {
            int i = tid;
            float s = 0.f;
            for (int d = 0; d < 64; d++) s += QsT[d * 64 + i] * kss[d];
            for (int j = 0; j <= i; j++) s += STs[j * 64 + i];
            den[i] = fmaxf(s, 1e-6f);
        }
        __syncthreads();
        // ---- out[i][m] = (Q.KV_prev + S.V) / denom ----
        {
            float acc[16];
#pragma unroll
            for (int z = 0; z < 16; z++) acc[z] = 0.f;
            for (int d = 0; d < 64; d++) {
                float4 qv = *(float4*)&QsT[d * 64 + g1 * 4];
                float4 kvv = *(float4*)&KV[d * 64 + g2 * 4];
                float qa[4] = {qv.x, qv.y, qv.z, qv.w};
                float ka[4] = {kvv.x, kvv.y, kvv.z, kvv.w};
#pragma unroll
                for (int ii = 0; ii < 4; ii++)
#pragma unroll
                    for (int mm = 0; mm < 4; mm++)
                        acc[ii * 4 + mm] += qa[ii] * ka[mm];
            }
            for (int j = 0; j < 64; j++) {
                float4 sv = *(float4*)&STs[j * 64 + g1 * 4];
                float4 vv = *(float4*)&Vs[j * 64 + g2 * 4];
                float sa[4] = {sv.x, sv.y, sv.z, sv.w};
                float va[4] = {vv.x, vv.y, vv.z, vv.w};
#pragma unroll
                for (int ii = 0; ii < 4; ii++)
#pragma unroll
                    for (int mm = 0; mm < 4; mm++)
                        acc[ii * 4 + mm] += sa[ii] * va[mm];
            }
#pragma unroll
            for (int ii = 0; ii < 4; ii++) {
                int i = g1 * 4 + ii;
                float inv = 1.f / den[i];
                float4 r = make_float4(acc[ii * 4 + 0] * inv, acc[ii * 4 + 1] * inv,
                                       acc[ii * 4 + 2] * inv, acc[ii * 4 + 3] * inv);
                *(float4*)(ob + (size_t)(n0 + i) * DIMM + g2 * 4) = r;
            }
        }
        __syncthreads();
        // ---- state update: KV += K^T V ; ks += colsum(K) ----
        {
            float acc[16];
#pragma unroll
            for (int dd = 0; dd < 4; dd++) {
                float4 t = *(float4*)&KV[(g1 * 4 + dd) * 64 + g2 * 4];
                acc[dd * 4 + 0] = t.x; acc[dd * 4 + 1] = t.y;
                acc[dd * 4 + 2] = t.z; acc[dd * 4 + 3] = t.w;
            }
            for (int i = 0; i < 64; i++) {
                float4 kk = *(float4*)&Ks[i * 64 + g1 * 4];
                float4 vv = *(float4*)&Vs[i * 64 + g2 * 4];
                float ka[4] = {kk.x, kk.y, kk.z, kk.w};
                float va[4] = {vv.x, vv.y, vv.z, vv.w};
#pragma unroll
                for (int dd = 0; dd < 4; dd++)
#pragma unroll
                    for (int mm = 0; mm < 4; mm++)
                        acc[dd * 4 + mm] += ka[dd] * va[mm];
            }
#pragma unroll
            for (int dd = 0; dd < 4; dd++) {
                float4 t = make_float4(acc[dd * 4 + 0], acc[dd * 4 + 1],
                                       acc[dd * 4 + 2], acc[dd * 4 + 3]);
                *(float4*)&KV[(g1 * 4 + dd) * 64 + g2 * 4] = t;
            }
            if (tid < 64) {
                int d = tid;
                float s = kss[d];
                for (int i = 0; i < 64; i++) s += Ks[i * 64 + d];
                kss[d] = s;
            }
        }
        __syncthreads();
    }
}

// ---------------- launch -----------------------------------------------------
extern "C" void kernel_launch(void* const* d_in, const int* in_sizes, int n_in,
                              void* d_out, int out_size) {
    const float* x    = (const float*)d_in[0];
    const float* wqkv = (const float*)d_in[1];
    const float* wout = (const float*)d_in[2];
    float* out = (float*)d_out;

    float *qkv, *qf, *kf, *vf;
    cudaGetSymbolAddress((void**)&qkv,  g_qkv);
    cudaGetSymbolAddress((void**)&qf,   g_qf);
    cudaGetSymbolAddress((void**)&kf,   g_kf);
    cudaGetSymbolAddress((void**)&vf,   g_vf);
    float* attn = qkv;  // alias: qkv is dead after rope_elu

    // 1) qkv = x @ w_qkv
    sgemm128<<<dim3(3 * DIMM / 128, ROWS / 128), 256>>>(x, wqkv, qkv,
                                                        ROWS, 3 * DIMM, DIMM);
    // 2) RoPE + ELU + transpose
    {
        int total = B_ * N_ * HEADS * 32;
        rope_elu<<<(total + 255) / 256, 256>>>(qkv, qf, kf, vf);
    }
    // 3) chunked linear attention (writes into the now-dead qkv buffer)
    cudaFuncSetAttribute(linattn, cudaFuncAttributeMaxDynamicSharedMemorySize,
                         ATTN_SMEM);
    linattn<<<B_ * HEADS, 256, ATTN_SMEM>>>(qf, kf, vf, attn);
    // 4) out = attn @ w_out
    sgemm128<<<dim3(DIMM / 128, ROWS / 128), 256>>>(attn, wout, out,
                                                    ROWS, DIMM, DIMM);
}

// round 7
// speedup vs baseline: 2.1539x; 2.1539x over previous
#include <cuda_runtime.h>
#include <cuda_bf16.h>
#include <math.h>
#include <stdint.h>

#define B_   4
#define N_   4096
#define DIMM 1024
#define HEADS 16
#define HD   64
#define ROWS (B_*N_)          // 16384

// ---------------- scratch (device globals: allocation-free) ----------------
__device__ float g_qkv[(size_t)ROWS * 3 * DIMM];        // qkv fp32; attn aliases
__device__ float g_qf [(size_t)B_*HEADS*N_*HD];
__device__ float g_kf [(size_t)B_*HEADS*N_*HD];
__device__ float g_vf [(size_t)B_*HEADS*N_*HD];
__device__ __nv_bfloat16 g_xh [(size_t)ROWS * DIMM];    // x split
__device__ __nv_bfloat16 g_xl [(size_t)ROWS * DIMM];
__device__ __nv_bfloat16 g_ah [(size_t)ROWS * DIMM];    // attn split
__device__ __nv_bfloat16 g_al [(size_t)ROWS * DIMM];
__device__ __nv_bfloat16 g_wqh[(size_t)3 * DIMM * DIMM]; // wqkv^T split [N][K]
__device__ __nv_bfloat16 g_wql[(size_t)3 * DIMM * DIMM];
__device__ __nv_bfloat16 g_woh[(size_t)DIMM * DIMM];     // wout^T split
__device__ __nv_bfloat16 g_wol[(size_t)DIMM * DIMM];

// ---------------- helpers ----------------------------------------------------
__device__ __forceinline__ uint32_t smem_u32(const void* p) {
    uint32_t a;
    asm("{ .reg .u64 t; cvta.to.shared.u64 t, %1; cvt.u32.u64 %0, t; }"
        : "=r"(a) : "l"(p));
    return a;
}
__device__ __forceinline__ void cp16(uint32_t s, const void* g) {
    asm volatile("cp.async.cg.shared.global [%0], [%1], 16;" :: "r"(s), "l"(g));
}
#define CP_COMMIT() asm volatile("cp.async.commit_group;" ::: "memory")
#define CP_WAIT(n)  asm volatile("cp.async.wait_group %0;" :: "n"(n) : "memory")
#define LDSM4(r0, r1, r2, r3, addr) asm volatile( \
    "ldmatrix.sync.aligned.m8n8.x4.shared.b16 {%0,%1,%2,%3}, [%4];" \
    : "=r"(r0), "=r"(r1), "=r"(r2), "=r"(r3) : "r"(addr))
__device__ __forceinline__ void mma16816(float* c, const uint32_t* a,
                                         const uint32_t* b) {
    asm volatile(
        "mma.sync.aligned.m16n8k16.row.col.f32.bf16.bf16.f32 "
        "{%0,%1,%2,%3}, {%4,%5,%6,%7}, {%8,%9}, {%0,%1,%2,%3};"
        : "+f"(c[0]), "+f"(c[1]), "+f"(c[2]), "+f"(c[3])
        : "r"(a[0]), "r"(a[1]), "r"(a[2]), "r"(a[3]), "r"(b[0]), "r"(b[1]));
}

// smem tile 128 rows x 32 bf16 (64B/row). Two rows share a 128B line; 16B unit
// position within the line is XOR-swizzled by (rowpair & 7) so cp.async stores
// and all ldmatrix reads are conflict-free.
__device__ __forceinline__ uint32_t swz(int r, int ck) {
    return (uint32_t)(((r >> 1) << 7) |
                      ((((((r & 1) << 2) | ck)) ^ ((r >> 1) & 7)) << 4));
}

// ---------------- split fp32 -> bf16 hi/lo ----------------------------------
__global__ void split_bf16(const float* __restrict__ in,
                           __nv_bfloat16* __restrict__ hi,
                           __nv_bfloat16* __restrict__ lo, int n4) {
    int i = blockIdx.x * blockDim.x + threadIdx.x;
    if (i >= n4) return;
    float4 v = ((const float4*)in)[i];
    __nv_bfloat16 h0 = __float2bfloat16(v.x), h1 = __float2bfloat16(v.y);
    __nv_bfloat16 h2 = __float2bfloat16(v.z), h3 = __float2bfloat16(v.w);
    __nv_bfloat16 l0 = __float2bfloat16(v.x - __bfloat162float(h0));
    __nv_bfloat16 l1 = __float2bfloat16(v.y - __bfloat162float(h1));
    __nv_bfloat16 l2 = __float2bfloat16(v.z - __bfloat162float(h2));
    __nv_bfloat16 l3 = __float2bfloat16(v.w - __bfloat162float(h3));
    ((ushort4*)hi)[i] = make_ushort4(__bfloat16_as_ushort(h0), __bfloat16_as_ushort(h1),
                                     __bfloat16_as_ushort(h2), __bfloat16_as_ushort(h3));
    ((ushort4*)lo)[i] = make_ushort4(__bfloat16_as_ushort(l0), __bfloat16_as_ushort(l1),
                                     __bfloat16_as_ushort(l2), __bfloat16_as_ushort(l3));
}

// ---------------- transpose + split: w[K][N] -> wt_hi/lo [N][K] --------------
__global__ void transpose_split(const float* __restrict__ w,
                                __nv_bfloat16* __restrict__ th,
                                __nv_bfloat16* __restrict__ tl, int K, int N) {
    __shared__ float t[32][33];
    int tx = threadIdx.x, ty = threadIdx.y;
    int x = blockIdx.x * 32 + tx;
#pragma unroll
    for (int j = 0; j < 32; j += 8) {
        int y = blockIdx.y * 32 + ty + j;
        t[ty + j][tx] = w[(size_t)y * N + x];
    }
    __syncthreads();
#pragma unroll
    for (int j = 0; j < 32; j += 8) {
        int n = blockIdx.x * 32 + ty + j;
        int k = blockIdx.y * 32 + tx;
        float v = t[tx][ty + j];
        __nv_bfloat16 h = __float2bfloat16(v);
        th[(size_t)n * K + k] = h;
        tl[(size_t)n * K + k] = __float2bfloat16(v - __bfloat162float(h));
    }
}

// ---------------- split-bf16 tensor-core GEMM (mma.sync, sm_80 path) ---------
// C[M,N] = A[M,K] * Bt[N,K]^T with A = Ah+Al, B = Bh+Bl (3-term compensation).
// 128x128 CTA tile, BK=32, 2-stage cp.async pipeline, 8 warps (2m x 4n).
#define STAGE    32768
#define OFFS_AH  0
#define OFFS_AL  8192
#define OFFS_BH  16384
#define OFFS_BL  24576
#define GEMM_SMEM (2 * STAGE)

__global__ void __launch_bounds__(256, 2) mma_gemm(
    const __nv_bfloat16* __restrict__ Ah, const __nv_bfloat16* __restrict__ Al,
    const __nv_bfloat16* __restrict__ Bh, const __nv_bfloat16* __restrict__ Bl,
    float* __restrict__ C, int M, int N, int K) {
    extern __shared__ char sm[];
    const uint32_t sb = smem_u32(sm);
    const int tid = threadIdx.x;
    const int lane = tid & 31, wid = tid >> 5;
    const int warp_m = wid & 1, warp_n = wid >> 1;
    const int m0 = blockIdx.y * 128, n0 = blockIdx.x * 128;

    // loader: 512 chunks of 16B per 8KB tensor; each thread does 2 chunks/tensor
    const int i0 = tid, i1 = tid + 256;
    const int lr0 = i0 >> 2, lc0 = i0 & 3;
    const int lr1 = i1 >> 2, lc1 = i1 & 3;
    const uint32_t so0 = swz(lr0, lc0), so1 = swz(lr1, lc1);

    // fragment ldmatrix base offsets (per lane), ks toggles via ^32
    uint32_t baseA[4], baseB[2];
#pragma unroll
    for (int mf = 0; mf < 4; mf++)
        baseA[mf] = swz(warp_m * 64 + mf * 16 + (lane & 15), lane >> 4);
#pragma unroll
    for (int p = 0; p < 2; p++)
        baseB[p] = swz(warp_n * 32 + p * 16 + ((lane >> 4) << 3) + (lane & 7),
                       (lane >> 3) & 1);

    float acc[4][4][4];
#pragma unroll
    for (int a = 0; a < 4; a++)
#pragma unroll
        for (int b = 0; b < 4; b++)
#pragma unroll
            for (int c = 0; c < 4; c++) acc[a][b][c] = 0.f;

    const int nIter = K >> 5;   // BK = 32
    // prologue: stage 0
    {
        uint32_t bs = sb;
        size_t a0 = (size_t)(m0 + lr0) * K + lc0 * 8;
        size_t a1 = (size_t)(m0 + lr1) * K + lc1 * 8;
        size_t b0 = (size_t)(n0 + lr0) * K + lc0 * 8;
        size_t b1 = (size_t)(n0 + lr1) * K + lc1 * 8;
        cp16(bs + OFFS_AH + so0, Ah + a0); cp16(bs + OFFS_AH + so1, Ah + a1);
        cp16(bs + OFFS_AL + so0, Al + a0); cp16(bs + OFFS_AL + so1, Al + a1);
        cp16(bs + OFFS_BH + so0, Bh + b0); cp16(bs + OFFS_BH + so1, Bh + b1);
        cp16(bs + OFFS_BL + so0, Bl + b0); cp16(bs + OFFS_BL + so1, Bl + b1);
        CP_COMMIT();
    }

    for (int it = 0; it < nIter; it++) {
        if (it + 1 < nIter) {
            int kk = (it + 1) << 5;
            uint32_t bs = sb + ((it + 1) & 1) * STAGE;
            size_t a0 = (size_t)(m0 + lr0) * K + kk + lc0 * 8;
            size_t a1 = (size_t)(m0 + lr1) * K + kk + lc1 * 8;
            size_t b0 = (size_t)(n0 + lr0) * K + kk + lc0 * 8;
            size_t b1 = (size_t)(n0 + lr1) * K + kk + lc1 * 8;
            cp16(bs + OFFS_AH + so0, Ah + a0); cp16(bs + OFFS_AH + so1, Ah + a1);
            cp16(bs + OFFS_AL + so0, Al + a0); cp16(bs + OFFS_AL + so1, Al + a1);
            cp16(bs + OFFS_BH + so0, Bh + b0); cp16(bs + OFFS_BH + so1, Bh + b1);
            cp16(bs + OFFS_BL + so0, Bl + b0); cp16(bs + OFFS_BL + so1, Bl + b1);
            CP_COMMIT();
            CP_WAIT(1);
        } else {
            CP_WAIT(0);
        }
        __syncthreads();

        const uint32_t ss = sb + (it & 1) * STAGE;
#pragma unroll
        for (int ks = 0; ks < 2; ks++) {
            const uint32_t kx = ks * 32;
            uint32_t bh[4][2], bl[4][2];
#pragma unroll
            for (int p = 0; p < 2; p++) {
                uint32_t r0, r1, r2, r3;
                LDSM4(r0, r1, r2, r3, ss + OFFS_BH + (baseB[p] ^ kx));
                bh[2 * p][0] = r0; bh[2 * p][1] = r1;
                bh[2 * p + 1][0] = r2; bh[2 * p + 1][1] = r3;
                LDSM4(r0, r1, r2, r3, ss + OFFS_BL + (baseB[p] ^ kx));
                bl[2 * p][0] = r0; bl[2 * p][1] = r1;
                bl[2 * p + 1][0] = r2; bl[2 * p + 1][1] = r3;
            }
#pragma unroll
            for (int mf = 0; mf < 4; mf++) {
                uint32_t ah[4], al[4];
                LDSM4(ah[0], ah[1], ah[2], ah[3], ss + OFFS_AH + (baseA[mf] ^ kx));
                LDSM4(al[0], al[1], al[2], al[3], ss + OFFS_AL + (baseA[mf] ^ kx));
#pragma unroll
                for (int nf = 0; nf < 4; nf++) {
                    mma16816(acc[mf][nf], ah, bh[nf]);
                    mma16816(acc[mf][nf], ah, bl[nf]);
                    mma16816(acc[mf][nf], al, bh[nf]);
                }
            }
        }
        __syncthreads();
    }

    // epilogue: direct stores (each lane: 2 floats per frag row)
#pragma unroll
    for (int mf = 0; mf < 4; mf++) {
#pragma unroll
        for (int nf = 0; nf < 4; nf++) {
            int row = m0 + warp_m * 64 + mf * 16 + (lane >> 2);
            int col = n0 + warp_n * 32 + nf * 8 + 2 * (lane & 3);
            *(float2*)(C + (size_t)row * N + col) =
                make_float2(acc[mf][nf][0], acc[mf][nf][1]);
            *(float2*)(C + (size_t)(row + 8) * N + col) =
                make_float2(acc[mf][nf][2], acc[mf][nf][3]);
        }
    }
}

// ---------------- RoPE + ELU feature map + transpose to (B,H,N,D) ----------
__global__ void rope_elu(const float* __restrict__ qkv,
                         float* __restrict__ qf, float* __restrict__ kf,
                         float* __restrict__ vf) {
    int idx = blockIdx.x * blockDim.x + threadIdx.x;
    const int total = B_ * N_ * HEADS * 32;
    if (idx >= total) return;
    const int d2 = idx & 31;
    const int h  = (idx >> 5) & 15;
    const int n  = (idx >> 9) & 4095;
    const int b  = idx >> 21;

    size_t base = (size_t)(b * N_ + n) * (3 * DIMM);
    int c1 = h * 64 + d2;
    float q1 = qkv[base + c1],            q2 = qkv[base + c1 + 32];
    float k1 = qkv[base + 1024 + c1],     k2 = qkv[base + 1024 + c1 + 32];
    float v1 = qkv[base + 2048 + c1],     v2 = qkv[base + 2048 + c1 + 32];

    float inv = powf(10000.f, -(float)d2 * (1.f / 32.f));
    float ang = (float)n * inv;
    float cs = cosf(ang), sn = sinf(ang);
    float qr1 = q1 * cs - q2 * sn, qr2 = q1 * sn + q2 * cs;
    float kr1 = k1 * cs - k2 * sn, kr2 = k1 * sn + k2 * cs;

    const float SC = 0.35355339059327373f;
    float y;
    y = qr1 * SC; float fq1 = (y > 0.f) ? y + 1.f : expf(y);
    y = qr2 * SC; float fq2 = (y > 0.f) ? y + 1.f : expf(y);
    y = kr1 * SC; float fk1 = (y > 0.f) ? y + 1.f : expf(y);
    y = kr2 * SC; float fk2 = (y > 0.f) ? y + 1.f : expf(y);

    size_t ob = ((size_t)(b * HEADS + h) * N_ + n) * HD;
    qf[ob + d2] = fq1;  qf[ob + d2 + 32] = fq2;
    kf[ob + d2] = fk1;  kf[ob + d2 + 32] = fk2;
    vf[ob + d2] = v1;   vf[ob + d2 + 32] = v2;
}

// ---------------- chunked causal linear attention ---------------------------
#define ATTN_SMEM (6 * 4096 * 4 + 128 * 4)
__global__ void __launch_bounds__(256) linattn(const float* __restrict__ qf,
                                               const float* __restrict__ kf,
                                               const float* __restrict__ vf,
                                               float* __restrict__ outp) {
    extern __shared__ float smf[];
    float* QsT = smf;
    float* Ks  = QsT + 4096;
    float* KsT = Ks + 4096;
    float* Vs  = KsT + 4096;
    float* STs = Vs + 4096;
    float* KV  = STs + 4096;
    float* kss = KV + 4096;
    float* den = kss + 64;

    const int tid = threadIdx.x;
    const int bh = blockIdx.x;
    const int b = bh >> 4, h = bh & 15;
    const float* qb = qf + (size_t)bh * N_ * HD;
    const float* kb = kf + (size_t)bh * N_ * HD;
    const float* vb = vf + (size_t)bh * N_ * HD;
    float* ob = outp + (size_t)b * N_ * DIMM + h * HD;

    for (int i = tid; i < 4096; i += 256) KV[i] = 0.f;
    if (tid < 64) kss[tid] = 0.f;
    __syncthreads();

    const int li = tid >> 2, lq = (tid & 3) * 16;
    const int g1 = tid >> 4, g2 = tid & 15;

    for (int c = 0; c < 64; c++) {
        const int n0 = c * 64;
        {
            const float* qrow = qb + (size_t)(n0 + li) * HD + lq;
            const float* krow = kb + (size_t)(n0 + li) * HD + lq;
            const float* vrow = vb + (size_t)(n0 + li) * HD + lq;
#pragma unroll
            for (int t = 0; t < 4; t++) {
                int d0 = lq + t * 4;
                float4 qv = *(const float4*)(qrow + t * 4);
                QsT[(d0 + 0) * 64 + li] = qv.x;
                QsT[(d0 + 1) * 64 + li] = qv.y;
                QsT[(d0 + 2) * 64 + li] = qv.z;
                QsT[(d0 + 3) * 64 + li] = qv.w;
                float4 kv4 = *(const float4*)(krow + t * 4);
                *(float4*)&Ks[li * 64 + d0] = kv4;
                KsT[(d0 + 0) * 64 + li] = kv4.x;
                KsT[(d0 + 1) * 64 + li] = kv4.y;
                KsT[(d0 + 2) * 64 + li] = kv4.z;
                KsT[(d0 + 3) * 64 + li] = kv4.w;
                float4 vv = *(const float4*)(vrow + t * 4);
                *(float4*)&Vs[li * 64 + d0] = vv;
            }
        }
        __syncthreads();
        {
            float accS[16];
#pragma unroll
            for (int z = 0; z < 16; z++) accS[z] = 0.f;
            for (int d = 0; d < 64; d++) {
                float4 qv = *(float4*)&QsT[d * 64 + g2 * 4];
                float4 kk = *(float4*)&KsT[d * 64 + g1 * 4];
                float qa[4] = {qv.x, qv.y, qv.z, qv.w};
                float ka[4] = {kk.x, kk.y, kk.z, kk.w};
#pragma unroll
                for (int jj = 0; jj < 4; jj++)
#pragma unroll
                    for (int ii = 0; ii < 4; ii++)
                        accS[jj * 4 + ii] += ka[jj] * qa[ii];
            }
#pragma unroll
            for (int jj = 0; jj < 4; jj++)
#pragma unroll
                for (int ii = 0; ii < 4; ii++) {
                    int j = g1 * 4 + jj, i = g2 * 4 + ii;
                    STs[j * 64 + i] = (j <= i) ? accS[jj * 4 + ii] : 0.f;
                }
        }
        __syncthreads();
        if (tid < 64) {
            int i = tid;
            float s = 0.f;
            for (int d = 0; d < 64; d++) s += QsT[d * 64 + i] * kss[d];
            for (int j = 0; j <= i; j++) s += STs[j * 64 + i];
            den[i] = fmaxf(s, 1e-6f);
        }
        __syncthreads();
        {
            float acc[16];
#pragma unroll
            for (int z = 0; z < 16; z++) acc[z] = 0.f;
            for (int d = 0; d < 64; d++) {
                float4 qv = *(float4*)&QsT[d * 64 + g1 * 4];
                float4 kvv = *(float4*)&KV[d * 64 + g2 * 4];
                float qa[4] = {qv.x, qv.y, qv.z, qv.w};
                float ka[4] = {kvv.x, kvv.y, kvv.z, kvv.w};
#pragma unroll
                for (int ii = 0; ii < 4; ii++)
#pragma unroll
                    for (int mm = 0; mm < 4; mm++)
                        acc[ii * 4 + mm] += qa[ii] * ka[mm];
            }
            for (int j = 0; j < 64; j++) {
                float4 sv = *(float4*)&STs[j * 64 + g1 * 4];
                float4 vv = *(float4*)&Vs[j * 64 + g2 * 4];
                float sa[4] = {sv.x, sv.y, sv.z, sv.w};
                float va[4] = {vv.x, vv.y, vv.z, vv.w};
#pragma unroll
                for (int ii = 0; ii < 4; ii++)
#pragma unroll
                    for (int mm = 0; mm < 4; mm++)
                        acc[ii * 4 + mm] += sa[ii] * va[mm];
            }
#pragma unroll
            for (int ii = 0; ii < 4; ii++) {
                int i = g1 * 4 + ii;
                float inv = 1.f / den[i];
                float4 rr = make_float4(acc[ii * 4 + 0] * inv, acc[ii * 4 + 1] * inv,
                                        acc[ii * 4 + 2] * inv, acc[ii * 4 + 3] * inv);
                *(float4*)(ob + (size_t)(n0 + i) * DIMM + g2 * 4) = rr;
            }
        }
        __syncthreads();
        {
            float acc[16];
#pragma unroll
            for (int dd = 0; dd < 4; dd++) {
                float4 t = *(float4*)&KV[(g1 * 4 + dd) * 64 + g2 * 4];
                acc[dd * 4 + 0] = t.x; acc[dd * 4 + 1] = t.y;
                acc[dd * 4 + 2] = t.z; acc[dd * 4 + 3] = t.w;
            }
            for (int i = 0; i < 64; i++) {
                float4 kk = *(float4*)&Ks[i * 64 + g1 * 4];
                float4 vv = *(float4*)&Vs[i * 64 + g2 * 4];
                float ka[4] = {kk.x, kk.y, kk.z, kk.w};
                float va[4] = {vv.x, vv.y, vv.z, vv.w};
#pragma unroll
                for (int dd = 0; dd < 4; dd++)
#pragma unroll
                    for (int mm = 0; mm < 4; mm++)
                        acc[dd * 4 + mm] += ka[dd] * va[mm];
            }
#pragma unroll
            for (int dd = 0; dd < 4; dd++) {
                float4 t = make_float4(acc[dd * 4 + 0], acc[dd * 4 + 1],
                                       acc[dd * 4 + 2], acc[dd * 4 + 3]);
                *(float4*)&KV[(g1 * 4 + dd) * 64 + g2 * 4] = t;
            }
            if (tid < 64) {
                int d = tid;
                float s = kss[d];
                for (int i = 0; i < 64; i++) s += Ks[i * 64 + d];
                kss[d] = s;
            }
        }
        __syncthreads();
    }
}

// ---------------- launch -----------------------------------------------------
extern "C" void kernel_launch(void* const* d_in, const int* in_sizes, int n_in,
                              void* d_out, int out_size) {
    const float* x    = (const float*)d_in[0];
    const float* wqkv = (const float*)d_in[1];
    const float* wout = (const float*)d_in[2];
    float* out = (float*)d_out;

    float *qkv, *qf, *kf, *vf;
    __nv_bfloat16 *xh, *xl, *ah, *al, *wqh, *wql, *woh, *wol;
    cudaGetSymbolAddress((void**)&qkv, g_qkv);
    cudaGetSymbolAddress((void**)&qf,  g_qf);
    cudaGetSymbolAddress((void**)&kf,  g_kf);
    cudaGetSymbolAddress((void**)&vf,  g_vf);
    cudaGetSymbolAddress((void**)&xh,  g_xh);
    cudaGetSymbolAddress((void**)&xl,  g_xl);
    cudaGetSymbolAddress((void**)&ah,  g_ah);
    cudaGetSymbolAddress((void**)&al,  g_al);
    cudaGetSymbolAddress((void**)&wqh, g_wqh);
    cudaGetSymbolAddress((void**)&wql, g_wql);
    cudaGetSymbolAddress((void**)&woh, g_woh);
    cudaGetSymbolAddress((void**)&wol, g_wol);
    float* attn = qkv;  // qkv storage is dead after rope_elu

    cudaFuncSetAttribute(mma_gemm, cudaFuncAttributeMaxDynamicSharedMemorySize,
                         GEMM_SMEM);
    cudaFuncSetAttribute(linattn, cudaFuncAttributeMaxDynamicSharedMemorySize,
                         ATTN_SMEM);

    // split x; transpose+split weights
    {
        int n4 = ROWS * DIMM / 4;
        split_bf16<<<(n4 + 255) / 256, 256>>>(x, xh, xl, n4);
        transpose_split<<<dim3(3 * DIMM / 32, DIMM / 32), dim3(32, 8)>>>(
            wqkv, wqh, wql, DIMM, 3 * DIMM);
        transpose_split<<<dim3(DIMM / 32, DIMM / 32), dim3(32, 8)>>>(
            wout, woh, wol, DIMM, DIMM);
    }
    // 1) qkv = x @ w_qkv   (tensor cores)
    mma_gemm<<<dim3(3 * DIMM / 128, ROWS / 128), 256, GEMM_SMEM>>>(
        xh, xl, wqh, wql, qkv, ROWS, 3 * DIMM, DIMM);
    // 2) RoPE + ELU + transpose
    {
        int total = B_ * N_ * HEADS * 32;
        rope_elu<<<(total + 255) / 256, 256>>>(qkv, qf, kf, vf);
    }
    // 3) chunked linear attention
    linattn<<<B_ * HEADS, 256, ATTN_SMEM>>>(qf, kf, vf, attn);
    // 4) split attn; out = attn @ w_out (tensor cores)
    {
        int n4 = ROWS * DIMM / 4;
        split_bf16<<<(n4 + 255) / 256, 256>>>(attn, ah, al, n4);
    }
    mma_gemm<<<dim3(DIMM / 128, ROWS / 128), 256, GEMM_SMEM>>>(
        ah, al, woh, wol, out, ROWS, DIMM, DIMM);
}